// round 17
// baseline (speedup 1.0000x reference)
#include <cuda_runtime.h>
#include <cuda_fp16.h>

#define BATCH 2
#define SEQ 384
#define HID 128
#define TABLE (2 * SEQ + 1)   // 769
#define F4H (4 * HID)         // 512

// W pre-transposed: g_Wt[table][f][h] = W[h][table*128 + f]  (256 KB, L2-resident)
__device__ float g_Wt[4][HID][HID];
// Folded per-table results: T[x][t][h] = pe_x[t] @ W_x^T  (+ bias folded into x=0)
__device__ float g_T[4][TABLE][HID];
// Fully fused table in fp16: T2[(d*8+sq)*8+sk][h] = relu(sum of 4 + b). 12.6 MB.
__device__ __half g_T2h[TABLE * 64 * HID];

// ---------------------------------------------------------------------------
// Stage 0: transpose W [128h][512f] -> g_Wt[4][128f][128h].
// ---------------------------------------------------------------------------
__global__ __launch_bounds__(256) void transpose_kernel(const float* __restrict__ W) {
    __shared__ float tile[32][33];
    const int f0 = blockIdx.x * 32;
    const int h0 = blockIdx.y * 32;
    const int tx = threadIdx.x;
    const int ty = threadIdx.y;

#pragma unroll
    for (int i = 0; i < 4; i++)
        tile[ty + 8 * i][tx] = W[(h0 + ty + 8 * i) * F4H + f0 + tx];
    __syncthreads();

    const int table = f0 >> 7;
#pragma unroll
    for (int i = 0; i < 4; i++) {
        int fp = (f0 & 127) + ty + 8 * i;
        g_Wt[table][fp][h0 + tx] = tile[tx][ty + 8 * i];
    }
}

// ---------------------------------------------------------------------------
// Stage 1: T[x] = pe_x @ W_x^T.  Grid (97, 4), block 256, 8 t-rows/block
// (R12 geometry).  ILP change: each thread runs TWO independent accumulator
// chains over the f-halves [0,64) and [64,128) -> chain depth 64, two LDGs
// in flight per iteration.  Warp reads contiguous 128B g_Wt lines (L1-hit
// broadcast across the 8 t-rows of the block).
// ---------------------------------------------------------------------------
__global__ __launch_bounds__(256) void table_gemm_kernel(
    const float* __restrict__ pe0, const float* __restrict__ pe1,
    const float* __restrict__ pe2, const float* __restrict__ pe3,
    const float* __restrict__ bias) {
    const int table = blockIdx.y;
    const int tbase = blockIdx.x * 8;
    const float* pe = (table == 0) ? pe0 : (table == 1) ? pe1 : (table == 2) ? pe2 : pe3;

    __shared__ float pe_s[8][129];

    for (int idx = threadIdx.x; idx < 8 * HID; idx += 256) {
        int t = idx >> 7, f = idx & 127;
        int gt = tbase + t;
        pe_s[t][f] = (gt < TABLE) ? pe[gt * HID + f] : 0.0f;
    }
    __syncthreads();

    const int w_id = threadIdx.x >> 5;
    const int lane = threadIdx.x & 31;
    const int tg = w_id >> 2;
    const int hq = w_id & 3;             // warp-uniform
    const int hg = lane >> 2;
    const int lt = lane & 3;
    const int t = tg * 4 + lt;           // 0..7
    const int h0 = (hq * 8 + hg) * 4;

    const float* __restrict__ wt = &g_Wt[table][0][0];

    float a0 = 0.f, a1 = 0.f, a2 = 0.f, a3 = 0.f;   // f in [0,64)
    float b0 = 0.f, b1 = 0.f, b2 = 0.f, b3 = 0.f;   // f in [64,128)
#pragma unroll 8
    for (int f = 0; f < 64; f++) {
        float alo = pe_s[t][f];
        float ahi = pe_s[t][f + 64];
        float4 wlo = __ldg((const float4*)&wt[f * HID + h0]);
        float4 whi = __ldg((const float4*)&wt[(f + 64) * HID + h0]);
        a0 += alo * wlo.x; a1 += alo * wlo.y; a2 += alo * wlo.z; a3 += alo * wlo.w;
        b0 += ahi * whi.x; b1 += ahi * whi.y; b2 += ahi * whi.z; b3 += ahi * whi.w;
    }

    const int gt = tbase + t;
    if (gt < TABLE) {
        float r0 = a0 + b0, r1 = a1 + b1, r2 = a2 + b2, r3 = a3 + b3;
        if (table == 0) {
            float4 bb = *(const float4*)&bias[h0];
            r0 += bb.x; r1 += bb.y; r2 += bb.z; r3 += bb.w;
        }
        *(float4*)&g_T[table][gt][h0] = make_float4(r0, r1, r2, r3);
    }
}

// ---------------------------------------------------------------------------
// Stage 1b: build fused fp16 table from SMEM-staged g_T slices.
// Grid (97, 2): block = 8-wide d-tile x 64 h-cols (z half).  (R12 geometry)
// All accumulation in fp32; single round-to-nearest at the fp16 store.
// ---------------------------------------------------------------------------
__global__ __launch_bounds__(256) void build_kernel() {
    __shared__ float4 sT[4][23][16];

    const int d0 = blockIdx.x * 8;
    const int z  = blockIdx.y;          // h-half: float4 cols [z*16, z*16+16)
    const int tid = threadIdx.x;

    for (int idx = tid; idx < 4 * 23 * 16; idx += 256) {
        int table = idx / (23 * 16);
        int rem = idx - table * (23 * 16);
        int slot = rem >> 4;
        int c = rem & 15;
        int gt = min(max(d0 - 7 + slot, 0), TABLE - 1);
        sT[table][slot][c] = __ldg((const float4*)g_T[table] + gt * 32 + z * 16 + c);
    }
    __syncthreads();

    const int w = tid >> 5;             // warp -> d = d0 + w
    const int lane = tid & 31;
    const int col = lane & 15;          // float4 col within half
    const int rep = lane >> 4;          // sk parity
    const int d = d0 + w;
    if (d >= TABLE) return;

    const float4 v0 = sT[0][w + 7][col];
    // T2 row = 32 uint2 (128 halves); this thread owns uint2 index z*16+col
    uint2* __restrict__ out2 = (uint2*)g_T2h + (d << 6) * 32 + z * 16 + col;

#pragma unroll
    for (int sq = 0; sq < 8; sq++) {
        float4 v2 = sT[2][w + 7 + sq][col];
        float4 b02;
        b02.x = v0.x + v2.x; b02.y = v0.y + v2.y;
        b02.z = v0.z + v2.z; b02.w = v0.w + v2.w;
#pragma unroll
        for (int step = 0; step < 4; step++) {
            int sk = 2 * step + rep;
            float4 v1 = sT[1][w + 7 - sk][col];
            float4 v3 = sT[3][w + 7 + sq - sk][col];
            float rx = fmaxf(b02.x + v1.x + v3.x, 0.0f);
            float ry = fmaxf(b02.y + v1.y + v3.y, 0.0f);
            float rz = fmaxf(b02.z + v1.z + v3.z, 0.0f);
            float rw = fmaxf(b02.w + v1.w + v3.w, 0.0f);
            __half2 p0 = __floats2half2_rn(rx, ry);
            __half2 p1 = __floats2half2_rn(rz, rw);
            uint2 pk;
            pk.x = *(unsigned*)&p0;
            pk.y = *(unsigned*)&p1;
            out2[((sq << 3) + sk) * 32] = pk;
        }
    }
}

// ---------------------------------------------------------------------------
// Stage 2: out[b,q,k,:] = fp32(T2h[(d,sq,sk)]). One 8B L2-resident gather
// per lane (2 wavefronts/row) + fp32 streaming store (4 wavefronts/row).
// ---------------------------------------------------------------------------
__global__ __launch_bounds__(256) void fuse_kernel(
    const int* __restrict__ pos_s, const int* __restrict__ pos_e,
    float* __restrict__ out) {
    const int warp = (blockIdx.x << 3) + (threadIdx.x >> 5);
    const int lane = threadIdx.x & 31;

    const int k = warp % SEQ;
    const int bq = warp / SEQ;            // b*SEQ + q
    const int bbase = (bq / SEQ) * SEQ;   // b*SEQ

    const int aq = __ldg(pos_s + bq);
    const int eq = __ldg(pos_e + bq);
    const int ck = __ldg(pos_s + bbase + k);
    const int dk = __ldg(pos_e + bbase + k);

    const int d  = aq - ck + SEQ;
    const int sq = eq - aq;               // in [0,7]
    const int sk = dk - ck;               // in [0,7]
    const int row = (d << 6) + (sq << 3) + sk;

    uint2 pk = __ldg((const uint2*)g_T2h + row * 32 + lane);
    float2 f0 = __half22float2(*(__half2*)&pk.x);
    float2 f1 = __half22float2(*(__half2*)&pk.y);
    float4 r = make_float4(f0.x, f0.y, f1.x, f1.y);

    __stcs((float4*)out + warp * 32 + lane, r);
}

extern "C" void kernel_launch(void* const* d_in, const int* in_sizes, int n_in,
                              void* d_out, int out_size) {
    const int* pos_s   = (const int*)d_in[0];
    const int* pos_e   = (const int*)d_in[1];
    const float* pe_ss = (const float*)d_in[2];
    const float* pe_se = (const float*)d_in[3];
    const float* pe_es = (const float*)d_in[4];
    const float* pe_ee = (const float*)d_in[5];
    const float* W     = (const float*)d_in[6];
    const float* bias  = (const float*)d_in[7];
    float* out = (float*)d_out;

    transpose_kernel<<<dim3(16, 4), dim3(32, 8)>>>(W);

    dim3 g1((TABLE + 7) / 8, 4);                   // 97 x 4 = 388 blocks
    table_gemm_kernel<<<g1, 256>>>(pe_ss, pe_se, pe_es, pe_ee, bias);

    build_kernel<<<dim3((TABLE + 7) / 8, 2), 256>>>();   // 194 blocks

    const int rows = BATCH * SEQ * SEQ;            // 294912
    fuse_kernel<<<rows / 8, 256>>>(pos_s, pos_e, out);
}